// round 12
// baseline (speedup 1.0000x reference)
#include <cuda_runtime.h>
#include <math.h>

#define NB   1024
#define SS   128
#define CIN  32
#define TOK  32          // tokens per tile (4 tiles per batch element)
#define AS   132         // activation row stride (AS/4 = 33 odd -> conflict-free float4)
#define AS4  33
#define XSTR 36
#define XS4  9
#define NT   512

#define CCONST 1.2f
#define SQC    1.0954451150103321f
#define MINN   1e-15f
#define MAXN   ((1.0f - 4e-3f) / SQC)

struct __align__(16) Smem {
    float Wsh[64 * 128];       // 32 KB: one 64-output chunk of weights
    float bufA[TOK * AS];
    float bufB[TOK * AS];
    float outE[TOK * AS];
    float outH[TOK * AS];
    float bufX[TOK * XSTR];
    float bsh[128];
    float ebsh[128];
    float accE[128];
    float accH[128];
    float wteSh[128];
    float wthSh[128];
    float w0a[TOK];
    float gHa[TOK];
    float f1[16];
    float eb2;
};

__device__ __forceinline__ float wsum(float v) {
#pragma unroll
    for (int o = 16; o; o >>= 1) v += __shfl_xor_sync(0xffffffffu, v, o);
    return v;
}

__device__ __forceinline__ float tanhc(float z) {
    return tanhf(fminf(fmaxf(z, -15.f), 15.f));
}
__device__ __forceinline__ float artanhc(float z) {
    return atanhf(fminf(fmaxf(z, -1.f + 1e-7f), 1.f - 1e-7f));
}

// Chunked tiled GEMM: out[t][j] = dot(in[t][:], W[j][:]) (+bias)(+relu)
// Two 64-output chunks (outputs padded to 128 with zero rows).
// mode: 0 = raw matvec, 1 = +bias, 2 = +bias+relu
// computeEb: warp0 additionally computes expmap0(bias) -> ebsh, eb2
__device__ void gemm(const float* __restrict__ Wg, const float* __restrict__ bg,
                     int OUT, int K, const float* __restrict__ actIn, int st4,
                     float* __restrict__ actOut, int mode, Smem& s, int tid,
                     bool computeEb)
{
    const int K4 = K >> 2;
    const int tx = tid & 7;          // token group: tokens tx + 8*i
    const int ty = tid >> 3;         // output row within chunk (0..63)
    const float4* act4 = reinterpret_cast<const float4*>(actIn);
    const float4* W4 = reinterpret_cast<const float4*>(Wg);
    float4* Ws4 = reinterpret_cast<float4*>(s.Wsh);

    if (bg && tid < 128) s.bsh[tid] = (tid < OUT) ? bg[tid] : 0.f;

#pragma unroll
    for (int chunk = 0; chunk < 2; chunk++) {
        const int base = chunk * 64;
        const int lim = (OUT - base) * K4;   // valid float4s in this chunk
        const int tot = 64 * K4;
        for (int i = tid; i < tot; i += NT)
            Ws4[i] = (i < lim) ? W4[base * K4 + i] : make_float4(0.f, 0.f, 0.f, 0.f);
        __syncthreads();

        if (chunk == 0 && computeEb && (tid >> 5) == 0) {
            int lane = tid & 31;
            float bv[4];
            float ss = 0.f;
#pragma unroll
            for (int i = 0; i < 4; i++) {
                int j = lane + 32 * i;
                bv[i] = s.bsh[j];
                ss += bv[i] * bv[i];
            }
            ss = wsum(ss);
            float nn = fmaxf(sqrtf(ss), MINN);
            float t  = tanhc(SQC * nn);
            float sc = t / (SQC * nn);
            float rn = t / SQC;
            float pf = (rn > MAXN) ? (MAXN / rn) : 1.f;
            sc *= pf; rn *= pf;
#pragma unroll
            for (int i = 0; i < 4; i++) s.ebsh[lane + 32 * i] = bv[i] * sc;
            if (lane == 0) s.eb2 = rn * rn;
        }

        float acc0 = 0.f, acc1 = 0.f, acc2 = 0.f, acc3 = 0.f;
        const float4* wrow = Ws4 + ty * K4;
#pragma unroll 2
        for (int k4 = 0; k4 < K4; k4++) {
            float4 w  = wrow[k4];
            float4 a0 = act4[tx * st4 + k4];
            float4 a1 = act4[(tx + 8) * st4 + k4];
            float4 a2 = act4[(tx + 16) * st4 + k4];
            float4 a3 = act4[(tx + 24) * st4 + k4];
            acc0 = fmaf(a0.x, w.x, acc0); acc0 = fmaf(a0.y, w.y, acc0);
            acc0 = fmaf(a0.z, w.z, acc0); acc0 = fmaf(a0.w, w.w, acc0);
            acc1 = fmaf(a1.x, w.x, acc1); acc1 = fmaf(a1.y, w.y, acc1);
            acc1 = fmaf(a1.z, w.z, acc1); acc1 = fmaf(a1.w, w.w, acc1);
            acc2 = fmaf(a2.x, w.x, acc2); acc2 = fmaf(a2.y, w.y, acc2);
            acc2 = fmaf(a2.z, w.z, acc2); acc2 = fmaf(a2.w, w.w, acc2);
            acc3 = fmaf(a3.x, w.x, acc3); acc3 = fmaf(a3.y, w.y, acc3);
            acc3 = fmaf(a3.z, w.z, acc3); acc3 = fmaf(a3.w, w.w, acc3);
        }

        const int jj = base + ty;
        float bv = (mode >= 1) ? s.bsh[jj] : 0.f;
        float v0 = acc0 + bv, v1 = acc1 + bv, v2 = acc2 + bv, v3 = acc3 + bv;
        if (mode == 2) {
            v0 = fmaxf(v0, 0.f); v1 = fmaxf(v1, 0.f);
            v2 = fmaxf(v2, 0.f); v3 = fmaxf(v3, 0.f);
        }
        actOut[tx * AS + jj]        = v0;
        actOut[(tx + 8) * AS + jj]  = v1;
        actOut[(tx + 16) * AS + jj] = v2;
        actOut[(tx + 24) * AS + jj] = v3;
        __syncthreads();
    }
}

// expmap0 of the 32-dim input tokens: bufX -> bufA
__device__ void expmap_xs(Smem& s, int tid)
{
    int w = tid >> 5, lane = tid & 31;
    for (int t = w; t < TOK; t += 16) {
        float u = s.bufX[t * XSTR + lane];   // lane < 32 == CIN
        float s2 = wsum(u * u);
        float nn = fmaxf(sqrtf(s2), MINN);
        float tt = tanhc(SQC * nn);
        float sc = tt / (SQC * nn);
        float rn = tt / SQC;
        float pf = (rn > MAXN) ? (MAXN / rn) : 1.f;
        s.bufA[t * AS + lane] = u * sc * pf;
    }
    __syncthreads();
}

// Rowwise part of p_linear (mobius matvec scaling + projx + mobius bias add + projx),
// followed by act: 0 = none, 1 = mob_relu, 2 = logmap0.
__device__ void plinear_rows(Smem& s, const float* __restrict__ xIn,
                             int K, int OUT, float* __restrict__ outPtr,
                             int tid, int act)
{
    int w = tid >> 5, lane = tid & 31;
    for (int t = w; t < TOK; t += 16) {
        float x2p = 0.f;
#pragma unroll
        for (int i = 0; i < 4; i++) {
            int kk = lane + 32 * i;
            float v = (kk < K) ? xIn[t * AS + kk] : 0.f;
            x2p += v * v;
        }
        float mxv[4], ebv[4];
        float m2p = 0.f, dp = 0.f;
#pragma unroll
        for (int i = 0; i < 4; i++) {
            int jj = lane + 32 * i;
            float mv = (jj < OUT) ? s.bufB[t * AS + jj] : 0.f;
            float ev = (jj < OUT) ? s.ebsh[jj] : 0.f;
            mxv[i] = mv; ebv[i] = ev;
            m2p += mv * mv;
            dp  += mv * ev;
        }
        float x2s = wsum(x2p);
        float m2s = wsum(m2p);
        float dps = wsum(dp);

        float xn  = fmaxf(sqrtf(x2s), MINN);
        float mxn = fmaxf(sqrtf(m2s), MINN);
        float r   = tanhc((mxn / xn) * artanhc(SQC * xn));
        float sc  = r / (mxn * SQC);
        if (m2s == 0.f) sc = 0.f;
        float rn  = sc * mxn;
        float pf  = (rn > MAXN) ? (MAXN / rn) : 1.f;   // projx #1
        sc *= pf; rn *= pf;

        // mobius_add(res, eb)
        float x2 = rn * rn;
        float xy = sc * dps;
        float y2 = s.eb2;
        float c1 = 1.f + 2.f * CCONST * xy + CCONST * y2;
        float c2 = 1.f - CCONST * x2;
        float den = 1.f + 2.f * CCONST * xy + CCONST * CCONST * x2 * y2;
        float invden = 1.f / fmaxf(den, MINN);

        float ov[4];
        float o2p = 0.f;
#pragma unroll
        for (int i = 0; i < 4; i++) {
            ov[i] = (c1 * sc * mxv[i] + c2 * ebv[i]) * invden;
            o2p += ov[i] * ov[i];
        }
        float o2s = wsum(o2p);
        float on  = fmaxf(sqrtf(o2s), MINN);
        float pf2 = (on > MAXN) ? (MAXN / on) : 1.f;   // projx #2
        on *= pf2;
#pragma unroll
        for (int i = 0; i < 4; i++) ov[i] *= pf2;

        if (act == 1) {
            // mob_relu: logmap0 -> relu -> expmap0(+projx)
            float yn = fmaxf(on, MINN);
            float ls = artanhc(SQC * yn) / (SQC * yn);
            float rv[4];
            float r2p = 0.f;
#pragma unroll
            for (int i = 0; i < 4; i++) {
                rv[i] = fmaxf(ls * ov[i], 0.f);
                r2p += rv[i] * rv[i];
            }
            float r2s = wsum(r2p);
            float rr = fmaxf(sqrtf(r2s), MINN);
            float es = tanhc(SQC * rr) / (SQC * rr);
            float vn = es * rr;
            float pf3 = (vn > MAXN) ? (MAXN / vn) : 1.f;
            es *= pf3;
#pragma unroll
            for (int i = 0; i < 4; i++) {
                int jj = lane + 32 * i;
                if (jj < OUT) outPtr[t * AS + jj] = es * rv[i];
            }
        } else if (act == 2) {
            // logmap0
            float m = fmaxf(on, MINN);
            float ls = artanhc(SQC * m) / (SQC * m);
#pragma unroll
            for (int i = 0; i < 4; i++) {
                int jj = lane + 32 * i;
                if (jj < OUT) outPtr[t * AS + jj] = ls * ov[i];
            }
        } else {
#pragma unroll
            for (int i = 0; i < 4; i++) {
                int jj = lane + 32 * i;
                if (jj < OUT) outPtr[t * AS + jj] = ov[i];
            }
        }
    }
    __syncthreads();
}

// Per-token attention scalars: w0 (euclid weight) and gH (combined
// mobius_scalar_mul + projx + logmap0 scalar for the hyperbolic branch).
__device__ void attn_scores(Smem& s, float btev, float bthv, int tid)
{
    int w = tid >> 5, lane = tid & 31;
    for (int t = w; t < TOK; t += 16) {
        float dse = 0.f, dsh = 0.f, h2 = 0.f;
#pragma unroll
        for (int i = 0; i < 4; i++) {
            int j = lane + 32 * i;
            float d = s.bufA[t * AS + j] - s.bufB[t * AS + j];  // tan_e - tan_h
            dse += d * s.wteSh[j];
            dsh += d * s.wthSh[j];
            float h = s.outH[t * AS + j];
            h2 += h * h;
        }
        dse = wsum(dse); dsh = wsum(dsh); h2 = wsum(h2);
        float ae = 0.5f * dse + btev;
        float ah = -0.5f * dsh + bthv;
        float w0 = 1.f / (1.f + expf(ah - ae));
        float w1 = 1.f / (1.f + expf(ae - ah));

        float nn = fmaxf(sqrtf(h2), MINN);
        float s1 = tanhc(w1 * artanhc(SQC * nn)) / (nn * SQC);
        float rn = s1 * nn;
        float pf = (rn > MAXN) ? (MAXN / rn) : 1.f;
        s1 *= pf; rn *= pf;
        float m  = fmaxf(rn, MINN);
        float gH = (artanhc(SQC * m) / (SQC * m)) * s1;
        if (lane == 0) { s.w0a[t] = w0; s.gHa[t] = gH; }
    }
    __syncthreads();
}

__device__ void pool(Smem& s, int tid)
{
    if (tid < 128) {
        float a = 0.f;
#pragma unroll 4
        for (int t = 0; t < TOK; t++) a += s.w0a[t] * s.outE[t * AS + tid];
        s.accE[tid] += a;
    } else if (tid < 256) {
        int j = tid - 128;
        float a = 0.f;
#pragma unroll 4
        for (int t = 0; t < TOK; t++) a += s.gHa[t] * s.outH[t * AS + j];
        s.accH[j] += a;
    }
    __syncthreads();
}

__global__ void __launch_bounds__(NT, 2) pmnn_kernel(
    const float* __restrict__ x,
    const float* __restrict__ We1, const float* __restrict__ be1,
    const float* __restrict__ We2, const float* __restrict__ be2,
    const float* __restrict__ We3, const float* __restrict__ be3,
    const float* __restrict__ Wh1, const float* __restrict__ bh1,
    const float* __restrict__ Wh2, const float* __restrict__ bh2,
    const float* __restrict__ Wh3, const float* __restrict__ bh3,
    const float* __restrict__ Wae, const float* __restrict__ bae,
    const float* __restrict__ Wah, const float* __restrict__ bah,
    const float* __restrict__ Wte, const float* __restrict__ bte,
    const float* __restrict__ Wth, const float* __restrict__ bth,
    const float* __restrict__ Wf1, const float* __restrict__ bf1,
    const float* __restrict__ Wf2, const float* __restrict__ bf2,
    float* __restrict__ out)
{
    extern __shared__ char raw[];
    Smem& s = *reinterpret_cast<Smem*>(raw);
    const int tid = threadIdx.x;
    const int b = blockIdx.x;

    if (tid < 128)      s.accE[tid] = 0.f;
    else if (tid < 256) s.accH[tid - 128] = 0.f;
    else if (tid < 384) s.wteSh[tid - 256] = Wte[tid - 256];
    else                s.wthSh[tid - 384] = Wth[tid - 384];
    float btev = bte[0];
    float bthv = bth[0];
    __syncthreads();

    for (int tile = 0; tile < 4; tile++) {
        // load & transpose xs tile: x[b][c][s] -> bufX[tl][c]
        const float* xb = x + (size_t)b * CIN * SS + tile * TOK;
        for (int idx = tid; idx < TOK * CIN; idx += NT) {
            int c = idx >> 5, tl = idx & 31;
            s.bufX[tl * XSTR + c] = xb[c * SS + tl];
        }
        __syncthreads();

        // ---- Euclidean branch ----
        gemm(We1, be1, 80, 32,   s.bufX, XS4, s.bufA, 2, s, tid, false);
        gemm(We2, be2, 104, 80,  s.bufA, AS4, s.bufB, 2, s, tid, false);
        gemm(We3, be3, 128, 104, s.bufB, AS4, s.outE, 2, s, tid, false);

        // ---- Poincare branch ----
        expmap_xs(s, tid);
        gemm(Wh1, bh1, 80, 32,   s.bufA, AS4, s.bufB, 0, s, tid, true);
        plinear_rows(s, s.bufA, 32, 80,  s.bufA, tid, 1);
        gemm(Wh2, bh2, 104, 80,  s.bufA, AS4, s.bufB, 0, s, tid, true);
        plinear_rows(s, s.bufA, 80, 104, s.bufA, tid, 1);
        gemm(Wh3, bh3, 128, 104, s.bufA, AS4, s.bufB, 0, s, tid, true);
        plinear_rows(s, s.bufA, 104, 128, s.outH, tid, 0);

        // ---- cross-manifold attention ----
        gemm(Wae, bae, 128, 128, s.outE, AS4, s.bufA, 1, s, tid, false);  // tan_e
        gemm(Wah, bah, 128, 128, s.outH, AS4, s.bufB, 0, s, tid, true);
        plinear_rows(s, s.outH, 128, 128, s.bufB, tid, 2);                // tan_h

        attn_scores(s, btev, bthv, tid);
        pool(s, tid);
    }

    // ---- classifier ----
    int w = tid >> 5, lane = tid & 31;
    if (w < 10) {
        float a = 0.f;
#pragma unroll
        for (int i = 0; i < 8; i++) {
            int j = lane + 32 * i;
            float o = (j < 128) ? s.accE[j] : s.accH[j - 128];
            a += (o * (1.f / 128.f)) * Wf1[w * 256 + j];
        }
        a = wsum(a);
        if (lane == 0) s.f1[w] = fmaxf(a + bf1[w], 0.f);
    }
    __syncthreads();
    if (tid < 10) {
        float a = bf2[tid];
#pragma unroll
        for (int m = 0; m < 10; m++) a += s.f1[m] * Wf2[tid * 10 + m];
        out[(size_t)b * 10 + tid] = a;
    }
}

extern "C" void kernel_launch(void* const* d_in, const int* in_sizes, int n_in,
                              void* d_out, int out_size)
{
    (void)in_sizes; (void)n_in; (void)out_size;
    const float* x   = (const float*)d_in[0];
    const float* We1 = (const float*)d_in[1];
    const float* be1 = (const float*)d_in[2];
    const float* We2 = (const float*)d_in[3];
    const float* be2 = (const float*)d_in[4];
    const float* We3 = (const float*)d_in[5];
    const float* be3 = (const float*)d_in[6];
    const float* Wh1 = (const float*)d_in[7];
    const float* bh1 = (const float*)d_in[8];
    const float* Wh2 = (const float*)d_in[9];
    const float* bh2 = (const float*)d_in[10];
    const float* Wh3 = (const float*)d_in[11];
    const float* bh3 = (const float*)d_in[12];
    const float* Wae = (const float*)d_in[13];
    const float* bae = (const float*)d_in[14];
    const float* Wah = (const float*)d_in[15];
    const float* bah = (const float*)d_in[16];
    const float* Wte = (const float*)d_in[17];
    const float* bte = (const float*)d_in[18];
    const float* Wth = (const float*)d_in[19];
    const float* bth = (const float*)d_in[20];
    const float* Wf1 = (const float*)d_in[21];
    const float* bf1 = (const float*)d_in[22];
    const float* Wf2 = (const float*)d_in[23];
    const float* bf2 = (const float*)d_in[24];
    float* out = (float*)d_out;

    cudaFuncSetAttribute(pmnn_kernel,
                         cudaFuncAttributeMaxDynamicSharedMemorySize,
                         (int)sizeof(Smem));
    pmnn_kernel<<<NB, NT, sizeof(Smem)>>>(
        x, We1, be1, We2, be2, We3, be3,
        Wh1, bh1, Wh2, bh2, Wh3, bh3,
        Wae, bae, Wah, bah, Wte, bte, Wth, bth,
        Wf1, bf1, Wf2, bf2, out);
}

// round 13
// speedup vs baseline: 1.7807x; 1.7807x over previous
#include <cuda_runtime.h>
#include <math.h>

#define NB   1024
#define SS   128
#define CIN  32
#define TOK  64          // tokens per half-tile (2 half-tiles per batch element)
#define AS   132         // activation row stride; AS/4=33 odd -> good float4 banking
#define AS4  33
#define XSTR 36
#define XS4  9
#define NT   512

#define CCONST 1.2f
#define SQC    1.0954451150103321f
#define MINN   1e-15f
#define MAXN   ((1.0f - 4e-3f) / SQC)

struct __align__(16) Smem {
    float Wsh[128 * 128];      // 64 KB, rows zero-padded to 128
    float bufA[TOK * AS];
    float bufB[TOK * AS];
    float outE[TOK * AS];
    float outH[TOK * AS];
    float bufX[TOK * XSTR];
    float bsh[128];
    float ebsh[128];
    float accE[128];
    float accH[128];
    float wteSh[128];
    float wthSh[128];
    float w0a[TOK];
    float gHa[TOK];
    float f1[16];
    float eb2;
};

__device__ __forceinline__ float wsum(float v) {
#pragma unroll
    for (int o = 16; o; o >>= 1) v += __shfl_xor_sync(0xffffffffu, v, o);
    return v;
}

__device__ __forceinline__ float tanhc(float z) {
    return tanhf(fminf(fmaxf(z, -15.f), 15.f));
}
__device__ __forceinline__ float artanhc(float z) {
    return atanhf(fminf(fmaxf(z, -1.f + 1e-7f), 1.f - 1e-7f));
}

__device__ __forceinline__ float fma4(float acc, float4 a, float4 w) {
    acc = fmaf(a.x, w.x, acc);
    acc = fmaf(a.y, w.y, acc);
    acc = fmaf(a.z, w.z, acc);
    acc = fmaf(a.w, w.w, acc);
    return acc;
}

// Tiled GEMM: out[t][j] = dot(in[t][:], W[j][:]) (+bias)(+relu)
// 4 tokens x 4 outputs per thread, float4 along k.
// mode: 0 = raw matvec, 1 = +bias, 2 = +bias+relu
// computeEb: warp0 additionally computes expmap0(bias) -> ebsh, eb2
__device__ void gemm(const float* __restrict__ Wg, const float* __restrict__ bg,
                     int OUT, int K, const float* __restrict__ actIn, int st4,
                     float* __restrict__ actOut, int mode, Smem& s, int tid,
                     bool computeEb)
{
    const int K4 = K >> 2;
    const float4* act4 = reinterpret_cast<const float4*>(actIn);
    const float4* W4 = reinterpret_cast<const float4*>(Wg);
    float4* Ws4 = reinterpret_cast<float4*>(s.Wsh);

    const int tot = 128 * K4;          // rows padded to 128
    const int lim = OUT * K4;
    for (int i = tid; i < tot; i += NT)
        Ws4[i] = (i < lim) ? W4[i] : make_float4(0.f, 0.f, 0.f, 0.f);
    if (bg && tid < 128) s.bsh[tid] = (tid < OUT) ? bg[tid] : 0.f;
    __syncthreads();

    if (computeEb && (tid >> 5) == 0) {
        int lane = tid & 31;
        float bv[4];
        float ss = 0.f;
#pragma unroll
        for (int i = 0; i < 4; i++) {
            bv[i] = s.bsh[lane + 32 * i];
            ss += bv[i] * bv[i];
        }
        ss = wsum(ss);
        float nn = fmaxf(sqrtf(ss), MINN);
        float t  = tanhc(SQC * nn);
        float sc = t / (SQC * nn);
        float rn = t / SQC;
        float pf = (rn > MAXN) ? (MAXN / rn) : 1.f;
        sc *= pf; rn *= pf;
#pragma unroll
        for (int i = 0; i < 4; i++) s.ebsh[lane + 32 * i] = bv[i] * sc;
        if (lane == 0) s.eb2 = rn * rn;
    }

    const int tx = tid & 15;          // tokens tx + 16*i
    const int ty = tid >> 4;          // outputs ty + 32*j
    float acc[4][4];
#pragma unroll
    for (int i = 0; i < 4; i++)
#pragma unroll
        for (int j = 0; j < 4; j++) acc[i][j] = 0.f;

    const float4* a0p = act4 + tx * st4;
    const float4* a1p = act4 + (tx + 16) * st4;
    const float4* a2p = act4 + (tx + 32) * st4;
    const float4* a3p = act4 + (tx + 48) * st4;
    const float4* w0p = Ws4 + ty * K4;
    const float4* w1p = Ws4 + (ty + 32) * K4;
    const float4* w2p = Ws4 + (ty + 64) * K4;
    const float4* w3p = Ws4 + (ty + 96) * K4;

#pragma unroll 2
    for (int k4 = 0; k4 < K4; k4++) {
        float4 a0 = a0p[k4], a1 = a1p[k4], a2 = a2p[k4], a3 = a3p[k4];
        float4 w0 = w0p[k4], w1 = w1p[k4], w2 = w2p[k4], w3 = w3p[k4];
        acc[0][0] = fma4(acc[0][0], a0, w0);
        acc[0][1] = fma4(acc[0][1], a0, w1);
        acc[0][2] = fma4(acc[0][2], a0, w2);
        acc[0][3] = fma4(acc[0][3], a0, w3);
        acc[1][0] = fma4(acc[1][0], a1, w0);
        acc[1][1] = fma4(acc[1][1], a1, w1);
        acc[1][2] = fma4(acc[1][2], a1, w2);
        acc[1][3] = fma4(acc[1][3], a1, w3);
        acc[2][0] = fma4(acc[2][0], a2, w0);
        acc[2][1] = fma4(acc[2][1], a2, w1);
        acc[2][2] = fma4(acc[2][2], a2, w2);
        acc[2][3] = fma4(acc[2][3], a2, w3);
        acc[3][0] = fma4(acc[3][0], a3, w0);
        acc[3][1] = fma4(acc[3][1], a3, w1);
        acc[3][2] = fma4(acc[3][2], a3, w2);
        acc[3][3] = fma4(acc[3][3], a3, w3);
    }

#pragma unroll
    for (int i = 0; i < 4; i++) {
        int t = tx + 16 * i;
#pragma unroll
        for (int j = 0; j < 4; j++) {
            int jj = ty + 32 * j;
            if (jj < OUT) {
                float v = acc[i][j];
                if (mode >= 1) v += s.bsh[jj];
                if (mode == 2) v = fmaxf(v, 0.f);
                actOut[t * AS + jj] = v;
            }
        }
    }
    __syncthreads();
}

// expmap0 of the 32-dim input tokens: bufX -> bufA
__device__ void expmap_xs(Smem& s, int tid)
{
    int w = tid >> 5, lane = tid & 31;
    for (int t = w; t < TOK; t += 16) {
        float u = s.bufX[t * XSTR + lane];   // lane < 32 == CIN
        float s2 = wsum(u * u);
        float nn = fmaxf(sqrtf(s2), MINN);
        float tt = tanhc(SQC * nn);
        float sc = tt / (SQC * nn);
        float rn = tt / SQC;
        float pf = (rn > MAXN) ? (MAXN / rn) : 1.f;
        s.bufA[t * AS + lane] = u * sc * pf;
    }
    __syncthreads();
}

// Rowwise part of p_linear (mobius matvec scaling + projx + mobius bias add + projx),
// followed by act: 0 = none, 1 = mob_relu, 2 = logmap0.
__device__ void plinear_rows(Smem& s, const float* __restrict__ xIn,
                             int K, int OUT, float* __restrict__ outPtr,
                             int tid, int act)
{
    int w = tid >> 5, lane = tid & 31;
    for (int t = w; t < TOK; t += 16) {
        float x2p = 0.f;
#pragma unroll
        for (int i = 0; i < 4; i++) {
            int kk = lane + 32 * i;
            float v = (kk < K) ? xIn[t * AS + kk] : 0.f;
            x2p += v * v;
        }
        float mxv[4], ebv[4];
        float m2p = 0.f, dp = 0.f;
#pragma unroll
        for (int i = 0; i < 4; i++) {
            int jj = lane + 32 * i;
            float mv = (jj < OUT) ? s.bufB[t * AS + jj] : 0.f;
            float ev = (jj < OUT) ? s.ebsh[jj] : 0.f;
            mxv[i] = mv; ebv[i] = ev;
            m2p += mv * mv;
            dp  += mv * ev;
        }
        float x2s = wsum(x2p);
        float m2s = wsum(m2p);
        float dps = wsum(dp);

        float xn  = fmaxf(sqrtf(x2s), MINN);
        float mxn = fmaxf(sqrtf(m2s), MINN);
        float r   = tanhc((mxn / xn) * artanhc(SQC * xn));
        float sc  = r / (mxn * SQC);
        if (m2s == 0.f) sc = 0.f;
        float rn  = sc * mxn;
        float pf  = (rn > MAXN) ? (MAXN / rn) : 1.f;   // projx #1
        sc *= pf; rn *= pf;

        // mobius_add(res, eb)
        float x2 = rn * rn;
        float xy = sc * dps;
        float y2 = s.eb2;
        float c1 = 1.f + 2.f * CCONST * xy + CCONST * y2;
        float c2 = 1.f - CCONST * x2;
        float den = 1.f + 2.f * CCONST * xy + CCONST * CCONST * x2 * y2;
        float invden = 1.f / fmaxf(den, MINN);

        float ov[4];
        float o2p = 0.f;
#pragma unroll
        for (int i = 0; i < 4; i++) {
            ov[i] = (c1 * sc * mxv[i] + c2 * ebv[i]) * invden;
            o2p += ov[i] * ov[i];
        }
        float o2s = wsum(o2p);
        float on  = fmaxf(sqrtf(o2s), MINN);
        float pf2 = (on > MAXN) ? (MAXN / on) : 1.f;   // projx #2
        on *= pf2;
#pragma unroll
        for (int i = 0; i < 4; i++) ov[i] *= pf2;

        if (act == 1) {
            // mob_relu: logmap0 -> relu -> expmap0(+projx)
            float yn = fmaxf(on, MINN);
            float ls = artanhc(SQC * yn) / (SQC * yn);
            float rv[4];
            float r2p = 0.f;
#pragma unroll
            for (int i = 0; i < 4; i++) {
                rv[i] = fmaxf(ls * ov[i], 0.f);
                r2p += rv[i] * rv[i];
            }
            float r2s = wsum(r2p);
            float rr = fmaxf(sqrtf(r2s), MINN);
            float es = tanhc(SQC * rr) / (SQC * rr);
            float vn = es * rr;
            float pf3 = (vn > MAXN) ? (MAXN / vn) : 1.f;
            es *= pf3;
#pragma unroll
            for (int i = 0; i < 4; i++) {
                int jj = lane + 32 * i;
                if (jj < OUT) outPtr[t * AS + jj] = es * rv[i];
            }
        } else if (act == 2) {
            // logmap0
            float m = fmaxf(on, MINN);
            float ls = artanhc(SQC * m) / (SQC * m);
#pragma unroll
            for (int i = 0; i < 4; i++) {
                int jj = lane + 32 * i;
                if (jj < OUT) outPtr[t * AS + jj] = ls * ov[i];
            }
        } else {
#pragma unroll
            for (int i = 0; i < 4; i++) {
                int jj = lane + 32 * i;
                if (jj < OUT) outPtr[t * AS + jj] = ov[i];
            }
        }
    }
    __syncthreads();
}

// Per-token attention scalars: w0 (euclid weight) and gH (combined
// mobius_scalar_mul + projx + logmap0 scalar for the hyperbolic branch).
__device__ void attn_scores(Smem& s, float btev, float bthv, int tid)
{
    int w = tid >> 5, lane = tid & 31;
    for (int t = w; t < TOK; t += 16) {
        float dse = 0.f, dsh = 0.f, h2 = 0.f;
#pragma unroll
        for (int i = 0; i < 4; i++) {
            int j = lane + 32 * i;
            float d = s.bufA[t * AS + j] - s.bufB[t * AS + j];  // tan_e - tan_h
            dse += d * s.wteSh[j];
            dsh += d * s.wthSh[j];
            float h = s.outH[t * AS + j];
            h2 += h * h;
        }
        dse = wsum(dse); dsh = wsum(dsh); h2 = wsum(h2);
        float ae = 0.5f * dse + btev;
        float ah = -0.5f * dsh + bthv;
        float w0 = 1.f / (1.f + expf(ah - ae));
        float w1 = 1.f / (1.f + expf(ae - ah));

        float nn = fmaxf(sqrtf(h2), MINN);
        float s1 = tanhc(w1 * artanhc(SQC * nn)) / (nn * SQC);
        float rn = s1 * nn;
        float pf = (rn > MAXN) ? (MAXN / rn) : 1.f;
        s1 *= pf; rn *= pf;
        float m  = fmaxf(rn, MINN);
        float gH = (artanhc(SQC * m) / (SQC * m)) * s1;
        if (lane == 0) { s.w0a[t] = w0; s.gHa[t] = gH; }
    }
    __syncthreads();
}

__device__ void pool(Smem& s, int tid)
{
    if (tid < 128) {
        float a = 0.f;
#pragma unroll 4
        for (int t = 0; t < TOK; t++) a += s.w0a[t] * s.outE[t * AS + tid];
        s.accE[tid] += a;
    } else if (tid < 256) {
        int j = tid - 128;
        float a = 0.f;
#pragma unroll 4
        for (int t = 0; t < TOK; t++) a += s.gHa[t] * s.outH[t * AS + j];
        s.accH[j] += a;
    }
    __syncthreads();
}

__global__ void __launch_bounds__(NT, 1) pmnn_kernel(
    const float* __restrict__ x,
    const float* __restrict__ We1, const float* __restrict__ be1,
    const float* __restrict__ We2, const float* __restrict__ be2,
    const float* __restrict__ We3, const float* __restrict__ be3,
    const float* __restrict__ Wh1, const float* __restrict__ bh1,
    const float* __restrict__ Wh2, const float* __restrict__ bh2,
    const float* __restrict__ Wh3, const float* __restrict__ bh3,
    const float* __restrict__ Wae, const float* __restrict__ bae,
    const float* __restrict__ Wah, const float* __restrict__ bah,
    const float* __restrict__ Wte, const float* __restrict__ bte,
    const float* __restrict__ Wth, const float* __restrict__ bth,
    const float* __restrict__ Wf1, const float* __restrict__ bf1,
    const float* __restrict__ Wf2, const float* __restrict__ bf2,
    float* __restrict__ out)
{
    extern __shared__ char raw[];
    Smem& s = *reinterpret_cast<Smem*>(raw);
    const int tid = threadIdx.x;
    const int b = blockIdx.x;

    if (tid < 128)      s.accE[tid] = 0.f;
    else if (tid < 256) s.accH[tid - 128] = 0.f;
    else if (tid < 384) s.wteSh[tid - 256] = Wte[tid - 256];
    else                s.wthSh[tid - 384] = Wth[tid - 384];
    float btev = bte[0];
    float bthv = bth[0];
    __syncthreads();

    for (int half = 0; half < 2; half++) {
        // load & transpose xs tile: x[b][c][s] -> bufX[tl][c]
        const float* xb = x + (size_t)b * CIN * SS + half * TOK;
        for (int idx = tid; idx < TOK * CIN; idx += NT) {
            int c = idx >> 6, tl = idx & 63;
            s.bufX[tl * XSTR + c] = xb[c * SS + tl];
        }
        __syncthreads();

        // ---- Euclidean branch ----
        gemm(We1, be1, 80, 32,   s.bufX, XS4, s.bufA, 2, s, tid, false);
        gemm(We2, be2, 104, 80,  s.bufA, AS4, s.bufB, 2, s, tid, false);
        gemm(We3, be3, 128, 104, s.bufB, AS4, s.outE, 2, s, tid, false);

        // ---- Poincare branch ----
        expmap_xs(s, tid);
        gemm(Wh1, bh1, 80, 32,   s.bufA, AS4, s.bufB, 0, s, tid, true);
        plinear_rows(s, s.bufA, 32, 80,  s.bufA, tid, 1);
        gemm(Wh2, bh2, 104, 80,  s.bufA, AS4, s.bufB, 0, s, tid, true);
        plinear_rows(s, s.bufA, 80, 104, s.bufA, tid, 1);
        gemm(Wh3, bh3, 128, 104, s.bufA, AS4, s.bufB, 0, s, tid, true);
        plinear_rows(s, s.bufA, 104, 128, s.outH, tid, 0);

        // ---- cross-manifold attention ----
        gemm(Wae, bae, 128, 128, s.outE, AS4, s.bufA, 1, s, tid, false);  // tan_e
        gemm(Wah, bah, 128, 128, s.outH, AS4, s.bufB, 0, s, tid, true);
        plinear_rows(s, s.outH, 128, 128, s.bufB, tid, 2);                // tan_h

        attn_scores(s, btev, bthv, tid);
        pool(s, tid);
    }

    // ---- classifier ----
    int w = tid >> 5, lane = tid & 31;
    if (w < 10) {
        float a = 0.f;
#pragma unroll
        for (int i = 0; i < 8; i++) {
            int j = lane + 32 * i;
            float o = (j < 128) ? s.accE[j] : s.accH[j - 128];
            a += (o * (1.f / 128.f)) * Wf1[w * 256 + j];
        }
        a = wsum(a);
        if (lane == 0) s.f1[w] = fmaxf(a + bf1[w], 0.f);
    }
    __syncthreads();
    if (tid < 10) {
        float a = bf2[tid];
#pragma unroll
        for (int m = 0; m < 10; m++) a += s.f1[m] * Wf2[tid * 10 + m];
        out[(size_t)b * 10 + tid] = a;
    }
}

extern "C" void kernel_launch(void* const* d_in, const int* in_sizes, int n_in,
                              void* d_out, int out_size)
{
    (void)in_sizes; (void)n_in; (void)out_size;
    const float* x   = (const float*)d_in[0];
    const float* We1 = (const float*)d_in[1];
    const float* be1 = (const float*)d_in[2];
    const float* We2 = (const float*)d_in[3];
    const float* be2 = (const float*)d_in[4];
    const float* We3 = (const float*)d_in[5];
    const float* be3 = (const float*)d_in[6];
    const float* Wh1 = (const float*)d_in[7];
    const float* bh1 = (const float*)d_in[8];
    const float* Wh2 = (const float*)d_in[9];
    const float* bh2 = (const float*)d_in[10];
    const float* Wh3 = (const float*)d_in[11];
    const float* bh3 = (const float*)d_in[12];
    const float* Wae = (const float*)d_in[13];
    const float* bae = (const float*)d_in[14];
    const float* Wah = (const float*)d_in[15];
    const float* bah = (const float*)d_in[16];
    const float* Wte = (const float*)d_in[17];
    const float* bte = (const float*)d_in[18];
    const float* Wth = (const float*)d_in[19];
    const float* bth = (const float*)d_in[20];
    const float* Wf1 = (const float*)d_in[21];
    const float* bf1 = (const float*)d_in[22];
    const float* Wf2 = (const float*)d_in[23];
    const float* bf2 = (const float*)d_in[24];
    float* out = (float*)d_out;

    cudaFuncSetAttribute(pmnn_kernel,
                         cudaFuncAttributeMaxDynamicSharedMemorySize,
                         (int)sizeof(Smem));
    pmnn_kernel<<<NB, NT, sizeof(Smem)>>>(
        x, We1, be1, We2, be2, We3, be3,
        Wh1, bh1, Wh2, bh2, Wh3, bh3,
        Wae, bae, Wah, bah, Wte, bte, Wth, bth,
        Wf1, bf1, Wf2, bf2, out);
}

// round 14
// speedup vs baseline: 1.9273x; 1.0823x over previous
#include <cuda_runtime.h>
#include <math.h>

#define NB   1024
#define SS   128
#define CIN  32
#define TOK  64          // tokens per half-tile (2 half-tiles per batch element)
#define AS   132         // activation row stride; AS/4=33 odd -> good float4 banking
#define AS4  33
#define XSTR 36
#define XS4  9
#define NT   512

#define CCONST 1.2f
#define SQC    1.0954451150103321f
#define MINN   1e-15f
#define MAXN   ((1.0f - 4e-3f) / SQC)

struct __align__(16) Smem {
    float Wsh[128 * 128];      // 64 KB, rows zero-padded to 128
    float bufA[TOK * AS];
    float bufB[TOK * AS];
    float outE[TOK * AS];
    float outH[TOK * AS];
    float bufX[TOK * XSTR];
    float bsh[128];
    float ebsh[128];
    float accE[128];
    float accH[128];
    float wteSh[128];
    float wthSh[128];
    float w0a[TOK];
    float gHa[TOK];
    float f1[16];
    float eb2;
};

__device__ __forceinline__ float wsum(float v) {
#pragma unroll
    for (int o = 16; o; o >>= 1) v += __shfl_xor_sync(0xffffffffu, v, o);
    return v;
}

// fast tanh with clip [-15,15]: (e-1)/(e+1), e = exp(2z). MUFU-based, ~1e-6 rel err
__device__ __forceinline__ float tanhc(float z) {
    z = fminf(fmaxf(z, -15.f), 15.f);
    float e = __expf(2.f * z);
    return __fdividef(e - 1.f, e + 1.f);
}
// fast atanh with geoopt clip: 0.5*log((1+x)/(1-x)). MUFU log, ~1e-6 level err
__device__ __forceinline__ float artanhc(float x) {
    x = fminf(fmaxf(x, -1.f + 1e-7f), 1.f - 1e-7f);
    return 0.5f * __logf(__fdividef(1.f + x, 1.f - x));
}

__device__ __forceinline__ float fma4(float acc, float4 a, float4 w) {
    acc = fmaf(a.x, w.x, acc);
    acc = fmaf(a.y, w.y, acc);
    acc = fmaf(a.z, w.z, acc);
    acc = fmaf(a.w, w.w, acc);
    return acc;
}

// Tiled GEMM: out[t][j] = dot(in[t][:], W[j][:]) (+bias)(+relu)
// 4 tokens x 4 outputs per thread, float4 along k.
// mode: 0 = raw matvec, 1 = +bias, 2 = +bias+relu
// computeEb: warp0 additionally computes expmap0(bias) -> ebsh, eb2
__device__ void gemm(const float* __restrict__ Wg, const float* __restrict__ bg,
                     int OUT, int K, const float* __restrict__ actIn, int st4,
                     float* __restrict__ actOut, int mode, Smem& s, int tid,
                     bool computeEb)
{
    const int K4 = K >> 2;
    const float4* act4 = reinterpret_cast<const float4*>(actIn);
    const float4* W4 = reinterpret_cast<const float4*>(Wg);
    float4* Ws4 = reinterpret_cast<float4*>(s.Wsh);

    const int tot = 128 * K4;          // rows padded to 128
    const int lim = OUT * K4;
    for (int i = tid; i < tot; i += NT)
        Ws4[i] = (i < lim) ? W4[i] : make_float4(0.f, 0.f, 0.f, 0.f);
    if (bg && tid < 128) s.bsh[tid] = (tid < OUT) ? bg[tid] : 0.f;
    __syncthreads();

    if (computeEb && (tid >> 5) == 0) {
        int lane = tid & 31;
        float bv[4];
        float ss = 0.f;
#pragma unroll
        for (int i = 0; i < 4; i++) {
            bv[i] = s.bsh[lane + 32 * i];
            ss += bv[i] * bv[i];
        }
        ss = wsum(ss);
        float nn = fmaxf(sqrtf(ss), MINN);
        float t  = tanhc(SQC * nn);
        float sc = __fdividef(t, SQC * nn);
        float rn = t * (1.f / SQC);
        float pf = (rn > MAXN) ? __fdividef(MAXN, rn) : 1.f;
        sc *= pf; rn *= pf;
#pragma unroll
        for (int i = 0; i < 4; i++) s.ebsh[lane + 32 * i] = bv[i] * sc;
        if (lane == 0) s.eb2 = rn * rn;
    }

    const int tx = tid & 15;          // tokens tx + 16*i
    const int ty = tid >> 4;          // outputs ty + 32*j
    float acc[4][4];
#pragma unroll
    for (int i = 0; i < 4; i++)
#pragma unroll
        for (int j = 0; j < 4; j++) acc[i][j] = 0.f;

    const float4* a0p = act4 + tx * st4;
    const float4* a1p = act4 + (tx + 16) * st4;
    const float4* a2p = act4 + (tx + 32) * st4;
    const float4* a3p = act4 + (tx + 48) * st4;
    const float4* w0p = Ws4 + ty * K4;
    const float4* w1p = Ws4 + (ty + 32) * K4;
    const float4* w2p = Ws4 + (ty + 64) * K4;
    const float4* w3p = Ws4 + (ty + 96) * K4;

#pragma unroll 2
    for (int k4 = 0; k4 < K4; k4++) {
        float4 a0 = a0p[k4], a1 = a1p[k4], a2 = a2p[k4], a3 = a3p[k4];
        float4 w0 = w0p[k4], w1 = w1p[k4], w2 = w2p[k4], w3 = w3p[k4];
        acc[0][0] = fma4(acc[0][0], a0, w0);
        acc[0][1] = fma4(acc[0][1], a0, w1);
        acc[0][2] = fma4(acc[0][2], a0, w2);
        acc[0][3] = fma4(acc[0][3], a0, w3);
        acc[1][0] = fma4(acc[1][0], a1, w0);
        acc[1][1] = fma4(acc[1][1], a1, w1);
        acc[1][2] = fma4(acc[1][2], a1, w2);
        acc[1][3] = fma4(acc[1][3], a1, w3);
        acc[2][0] = fma4(acc[2][0], a2, w0);
        acc[2][1] = fma4(acc[2][1], a2, w1);
        acc[2][2] = fma4(acc[2][2], a2, w2);
        acc[2][3] = fma4(acc[2][3], a2, w3);
        acc[3][0] = fma4(acc[3][0], a3, w0);
        acc[3][1] = fma4(acc[3][1], a3, w1);
        acc[3][2] = fma4(acc[3][2], a3, w2);
        acc[3][3] = fma4(acc[3][3], a3, w3);
    }

#pragma unroll
    for (int i = 0; i < 4; i++) {
        int t = tx + 16 * i;
#pragma unroll
        for (int j = 0; j < 4; j++) {
            int jj = ty + 32 * j;
            if (jj < OUT) {
                float v = acc[i][j];
                if (mode >= 1) v += s.bsh[jj];
                if (mode == 2) v = fmaxf(v, 0.f);
                actOut[t * AS + jj] = v;
            }
        }
    }
    __syncthreads();
}

// expmap0 of the 32-dim input tokens: bufX -> bufA
__device__ void expmap_xs(Smem& s, int tid)
{
    int w = tid >> 5, lane = tid & 31;
#pragma unroll
    for (int t = w; t < TOK; t += 16) {
        float u = s.bufX[t * XSTR + lane];   // lane < 32 == CIN
        float s2 = wsum(u * u);
        float nn = fmaxf(sqrtf(s2), MINN);
        float tt = tanhc(SQC * nn);
        float sc = __fdividef(tt, SQC * nn);
        float rn = tt * (1.f / SQC);
        float pf = (rn > MAXN) ? __fdividef(MAXN, rn) : 1.f;
        s.bufA[t * AS + lane] = u * sc * pf;
    }
    __syncthreads();
}

// Rowwise part of p_linear (mobius matvec scaling + projx + mobius bias add + projx),
// followed by act: 0 = none, 1 = mob_relu, 2 = logmap0.
__device__ void plinear_rows(Smem& s, const float* __restrict__ xIn,
                             int K, int OUT, float* __restrict__ outPtr,
                             int tid, int act)
{
    int w = tid >> 5, lane = tid & 31;
#pragma unroll
    for (int t = w; t < TOK; t += 16) {
        float x2p = 0.f;
#pragma unroll
        for (int i = 0; i < 4; i++) {
            int kk = lane + 32 * i;
            float v = (kk < K) ? xIn[t * AS + kk] : 0.f;
            x2p += v * v;
        }
        float mxv[4], ebv[4];
        float m2p = 0.f, dp = 0.f;
#pragma unroll
        for (int i = 0; i < 4; i++) {
            int jj = lane + 32 * i;
            float mv = (jj < OUT) ? s.bufB[t * AS + jj] : 0.f;
            float ev = (jj < OUT) ? s.ebsh[jj] : 0.f;
            mxv[i] = mv; ebv[i] = ev;
            m2p += mv * mv;
            dp  += mv * ev;
        }
        float x2s = wsum(x2p);
        float m2s = wsum(m2p);
        float dps = wsum(dp);

        float xn  = fmaxf(sqrtf(x2s), MINN);
        float mxn = fmaxf(sqrtf(m2s), MINN);
        float r   = tanhc(__fdividef(mxn, xn) * artanhc(SQC * xn));
        float sc  = __fdividef(r, mxn * SQC);
        if (m2s == 0.f) sc = 0.f;
        float rn  = sc * mxn;
        float pf  = (rn > MAXN) ? __fdividef(MAXN, rn) : 1.f;   // projx #1
        sc *= pf; rn *= pf;

        // mobius_add(res, eb)
        float x2 = rn * rn;
        float xy = sc * dps;
        float y2 = s.eb2;
        float c1 = 1.f + 2.f * CCONST * xy + CCONST * y2;
        float c2 = 1.f - CCONST * x2;
        float den = 1.f + 2.f * CCONST * xy + CCONST * CCONST * x2 * y2;
        float invden = __fdividef(1.f, fmaxf(den, MINN));

        float ov[4];
        float o2p = 0.f;
#pragma unroll
        for (int i = 0; i < 4; i++) {
            ov[i] = (c1 * sc * mxv[i] + c2 * ebv[i]) * invden;
            o2p += ov[i] * ov[i];
        }
        float o2s = wsum(o2p);
        float on  = fmaxf(sqrtf(o2s), MINN);
        float pf2 = (on > MAXN) ? __fdividef(MAXN, on) : 1.f;   // projx #2
        on *= pf2;
#pragma unroll
        for (int i = 0; i < 4; i++) ov[i] *= pf2;

        if (act == 1) {
            // mob_relu: logmap0 -> relu -> expmap0(+projx)
            float yn = fmaxf(on, MINN);
            float ls = __fdividef(artanhc(SQC * yn), SQC * yn);
            float rv[4];
            float r2p = 0.f;
#pragma unroll
            for (int i = 0; i < 4; i++) {
                rv[i] = fmaxf(ls * ov[i], 0.f);
                r2p += rv[i] * rv[i];
            }
            float r2s = wsum(r2p);
            float rr = fmaxf(sqrtf(r2s), MINN);
            float es = __fdividef(tanhc(SQC * rr), SQC * rr);
            float vn = es * rr;
            float pf3 = (vn > MAXN) ? __fdividef(MAXN, vn) : 1.f;
            es *= pf3;
#pragma unroll
            for (int i = 0; i < 4; i++) {
                int jj = lane + 32 * i;
                if (jj < OUT) outPtr[t * AS + jj] = es * rv[i];
            }
        } else if (act == 2) {
            // logmap0
            float m = fmaxf(on, MINN);
            float ls = __fdividef(artanhc(SQC * m), SQC * m);
#pragma unroll
            for (int i = 0; i < 4; i++) {
                int jj = lane + 32 * i;
                if (jj < OUT) outPtr[t * AS + jj] = ls * ov[i];
            }
        } else {
#pragma unroll
            for (int i = 0; i < 4; i++) {
                int jj = lane + 32 * i;
                if (jj < OUT) outPtr[t * AS + jj] = ov[i];
            }
        }
    }
    __syncthreads();
}

// Per-token attention scalars: w0 (euclid weight) and gH (combined
// mobius_scalar_mul + projx + logmap0 scalar for the hyperbolic branch).
__device__ void attn_scores(Smem& s, float btev, float bthv, int tid)
{
    int w = tid >> 5, lane = tid & 31;
#pragma unroll
    for (int t = w; t < TOK; t += 16) {
        float dse = 0.f, dsh = 0.f, h2 = 0.f;
#pragma unroll
        for (int i = 0; i < 4; i++) {
            int j = lane + 32 * i;
            float d = s.bufA[t * AS + j] - s.bufB[t * AS + j];  // tan_e - tan_h
            dse += d * s.wteSh[j];
            dsh += d * s.wthSh[j];
            float h = s.outH[t * AS + j];
            h2 += h * h;
        }
        dse = wsum(dse); dsh = wsum(dsh); h2 = wsum(h2);
        float ae = 0.5f * dse + btev;
        float ah = -0.5f * dsh + bthv;
        float w0 = __fdividef(1.f, 1.f + __expf(ah - ae));
        float w1 = __fdividef(1.f, 1.f + __expf(ae - ah));

        float nn = fmaxf(sqrtf(h2), MINN);
        float s1 = __fdividef(tanhc(w1 * artanhc(SQC * nn)), nn * SQC);
        float rn = s1 * nn;
        float pf = (rn > MAXN) ? __fdividef(MAXN, rn) : 1.f;
        s1 *= pf; rn *= pf;
        float m  = fmaxf(rn, MINN);
        float gH = __fdividef(artanhc(SQC * m), SQC * m) * s1;
        if (lane == 0) { s.w0a[t] = w0; s.gHa[t] = gH; }
    }
    __syncthreads();
}

__device__ void pool(Smem& s, int tid)
{
    if (tid < 128) {
        float a0 = 0.f, a1 = 0.f, a2 = 0.f, a3 = 0.f;
#pragma unroll 4
        for (int t = 0; t < TOK; t += 4) {
            a0 += s.w0a[t]     * s.outE[t * AS + tid];
            a1 += s.w0a[t + 1] * s.outE[(t + 1) * AS + tid];
            a2 += s.w0a[t + 2] * s.outE[(t + 2) * AS + tid];
            a3 += s.w0a[t + 3] * s.outE[(t + 3) * AS + tid];
        }
        s.accE[tid] += (a0 + a1) + (a2 + a3);
    } else if (tid < 256) {
        int j = tid - 128;
        float a0 = 0.f, a1 = 0.f, a2 = 0.f, a3 = 0.f;
#pragma unroll 4
        for (int t = 0; t < TOK; t += 4) {
            a0 += s.gHa[t]     * s.outH[t * AS + j];
            a1 += s.gHa[t + 1] * s.outH[(t + 1) * AS + j];
            a2 += s.gHa[t + 2] * s.outH[(t + 2) * AS + j];
            a3 += s.gHa[t + 3] * s.outH[(t + 3) * AS + j];
        }
        s.accH[j] += (a0 + a1) + (a2 + a3);
    }
    __syncthreads();
}

__global__ void __launch_bounds__(NT, 1) pmnn_kernel(
    const float* __restrict__ x,
    const float* __restrict__ We1, const float* __restrict__ be1,
    const float* __restrict__ We2, const float* __restrict__ be2,
    const float* __restrict__ We3, const float* __restrict__ be3,
    const float* __restrict__ Wh1, const float* __restrict__ bh1,
    const float* __restrict__ Wh2, const float* __restrict__ bh2,
    const float* __restrict__ Wh3, const float* __restrict__ bh3,
    const float* __restrict__ Wae, const float* __restrict__ bae,
    const float* __restrict__ Wah, const float* __restrict__ bah,
    const float* __restrict__ Wte, const float* __restrict__ bte,
    const float* __restrict__ Wth, const float* __restrict__ bth,
    const float* __restrict__ Wf1, const float* __restrict__ bf1,
    const float* __restrict__ Wf2, const float* __restrict__ bf2,
    float* __restrict__ out)
{
    extern __shared__ char raw[];
    Smem& s = *reinterpret_cast<Smem*>(raw);
    const int tid = threadIdx.x;
    const int b = blockIdx.x;

    if (tid < 128)      s.accE[tid] = 0.f;
    else if (tid < 256) s.accH[tid - 128] = 0.f;
    else if (tid < 384) s.wteSh[tid - 256] = Wte[tid - 256];
    else                s.wthSh[tid - 384] = Wth[tid - 384];
    float btev = bte[0];
    float bthv = bth[0];
    __syncthreads();

    for (int half = 0; half < 2; half++) {
        // load & transpose xs tile: x[b][c][s] -> bufX[tl][c]
        const float* xb = x + (size_t)b * CIN * SS + half * TOK;
        for (int idx = tid; idx < TOK * CIN; idx += NT) {
            int c = idx >> 6, tl = idx & 63;
            s.bufX[tl * XSTR + c] = xb[c * SS + tl];
        }
        __syncthreads();

        // ---- Euclidean branch ----
        gemm(We1, be1, 80, 32,   s.bufX, XS4, s.bufA, 2, s, tid, false);
        gemm(We2, be2, 104, 80,  s.bufA, AS4, s.bufB, 2, s, tid, false);
        gemm(We3, be3, 128, 104, s.bufB, AS4, s.outE, 2, s, tid, false);

        // ---- Poincare branch ----
        expmap_xs(s, tid);
        gemm(Wh1, bh1, 80, 32,   s.bufA, AS4, s.bufB, 0, s, tid, true);
        plinear_rows(s, s.bufA, 32, 80,  s.bufA, tid, 1);
        gemm(Wh2, bh2, 104, 80,  s.bufA, AS4, s.bufB, 0, s, tid, true);
        plinear_rows(s, s.bufA, 80, 104, s.bufA, tid, 1);
        gemm(Wh3, bh3, 128, 104, s.bufA, AS4, s.bufB, 0, s, tid, true);
        plinear_rows(s, s.bufA, 104, 128, s.outH, tid, 0);

        // ---- cross-manifold attention ----
        gemm(Wae, bae, 128, 128, s.outE, AS4, s.bufA, 1, s, tid, false);  // tan_e
        gemm(Wah, bah, 128, 128, s.outH, AS4, s.bufB, 0, s, tid, true);
        plinear_rows(s, s.outH, 128, 128, s.bufB, tid, 2);                // tan_h

        attn_scores(s, btev, bthv, tid);
        pool(s, tid);
    }

    // ---- classifier ----
    int w = tid >> 5, lane = tid & 31;
    if (w < 10) {
        float a = 0.f;
#pragma unroll
        for (int i = 0; i < 8; i++) {
            int j = lane + 32 * i;
            float o = (j < 128) ? s.accE[j] : s.accH[j - 128];
            a += (o * (1.f / 128.f)) * Wf1[w * 256 + j];
        }
        a = wsum(a);
        if (lane == 0) s.f1[w] = fmaxf(a + bf1[w], 0.f);
    }
    __syncthreads();
    if (tid < 10) {
        float a = bf2[tid];
#pragma unroll
        for (int m = 0; m < 10; m++) a += s.f1[m] * Wf2[tid * 10 + m];
        out[(size_t)b * 10 + tid] = a;
    }
}

extern "C" void kernel_launch(void* const* d_in, const int* in_sizes, int n_in,
                              void* d_out, int out_size)
{
    (void)in_sizes; (void)n_in; (void)out_size;
    const float* x   = (const float*)d_in[0];
    const float* We1 = (const float*)d_in[1];
    const float* be1 = (const float*)d_in[2];
    const float* We2 = (const float*)d_in[3];
    const float* be2 = (const float*)d_in[4];
    const float* We3 = (const float*)d_in[5];
    const float* be3 = (const float*)d_in[6];
    const float* Wh1 = (const float*)d_in[7];
    const float* bh1 = (const float*)d_in[8];
    const float* Wh2 = (const float*)d_in[9];
    const float* bh2 = (const float*)d_in[10];
    const float* Wh3 = (const float*)d_in[11];
    const float* bh3 = (const float*)d_in[12];
    const float* Wae = (const float*)d_in[13];
    const float* bae = (const float*)d_in[14];
    const float* Wah = (const float*)d_in[15];
    const float* bah = (const float*)d_in[16];
    const float* Wte = (const float*)d_in[17];
    const float* bte = (const float*)d_in[18];
    const float* Wth = (const float*)d_in[19];
    const float* bth = (const float*)d_in[20];
    const float* Wf1 = (const float*)d_in[21];
    const float* bf1 = (const float*)d_in[22];
    const float* Wf2 = (const float*)d_in[23];
    const float* bf2 = (const float*)d_in[24];
    float* out = (float*)d_out;

    cudaFuncSetAttribute(pmnn_kernel,
                         cudaFuncAttributeMaxDynamicSharedMemorySize,
                         (int)sizeof(Smem));
    pmnn_kernel<<<NB, NT, sizeof(Smem)>>>(
        x, We1, be1, We2, be2, We3, be3,
        Wh1, bh1, Wh2, bh2, Wh3, bh3,
        Wae, bae, Wah, bah, Wte, bte, Wth, bth,
        Wf1, bf1, Wf2, bf2, out);
}